// round 16
// baseline (speedup 1.0000x reference)
#include <cuda_runtime.h>
#include <cuda_bf16.h>
#include <cstdint>

#define Bn 4096
#define Sn 64
#define Fn 8
#define Dn 64
#define Kn 16
#define Ln 4096
#define PN (Bn*Sn*Fn)
#define TK_CAP 192

// ---------------- device scratch ----------------
__device__ __nv_bfloat16   g_xenc_bf16[Bn * Ln];         // 32 MB
__device__ float           g_gram[Bn * Bn];              // 64 MB
__device__ int             g_topidx[Bn * Kn];
__device__ float           g_c2[Bn];
__device__ float           g_part_mse[8192];
__device__ float           g_part_d1[Bn];
__device__ float           g_part_d2[Bn];
__device__ float           g_Weff[Fn * Fn];
__device__ float           g_beff[Fn];
__device__ float           g_P[PN];                      // fallback

// ---------------- helpers ----------------
__device__ __forceinline__ float block_reduce_sum(float v, float* s) {
    int t = threadIdx.x;
    s[t] = v;
    __syncthreads();
    for (int k = blockDim.x >> 1; k > 0; k >>= 1) {
        if (t < k) s[t] += s[t + k];
        __syncthreads();
    }
    return s[0];
}

__device__ __forceinline__ void cp_async16(uint32_t dst, const void* src) {
    asm volatile("cp.async.cg.shared.global [%0], [%1], 16;\n" :: "r"(dst), "l"(src) : "memory");
}

__device__ __forceinline__ void mma16816(float* c, const uint32_t* a, const uint32_t* b) {
    asm volatile(
        "mma.sync.aligned.m16n8k16.row.col.f32.bf16.bf16.f32 "
        "{%0,%1,%2,%3}, {%4,%5,%6,%7}, {%8,%9}, {%0,%1,%2,%3};"
        : "+f"(c[0]), "+f"(c[1]), "+f"(c[2]), "+f"(c[3])
        : "r"(a[0]), "r"(a[1]), "r"(a[2]), "r"(a[3]), "r"(b[0]), "r"(b[1]));
}

__device__ __forceinline__ void ldsm_x4(uint32_t* r, uint32_t addr) {
    asm volatile("ldmatrix.sync.aligned.m8n8.x4.shared.b16 {%0,%1,%2,%3}, [%4];"
                 : "=r"(r[0]), "=r"(r[1]), "=r"(r[2]), "=r"(r[3]) : "r"(addr));
}

// monotone float->u32 transform: larger float -> larger uint
__device__ __forceinline__ uint32_t fkey(float v) {
    uint32_t b = __float_as_uint(v);
    return b ^ ((b >> 31) ? 0xFFFFFFFFu : 0x80000000u);
}

// ---------------- 0) W_eff = W_emb @ W_proj ; b_eff ----------------
__global__ void weff_kernel(const float* __restrict__ Wemb,
                            const float* __restrict__ bemb,
                            const float* __restrict__ Wproj,
                            const float* __restrict__ bproj) {
    int t = threadIdx.x;
    int g = t >> 3, f = t & 7;
    float acc = 0.f;
#pragma unroll
    for (int d = 0; d < Dn; d++) acc += Wemb[g * Dn + d] * Wproj[d * Fn + f];
    g_Weff[g * Fn + f] = acc;
    if (t < Fn) {
        float b = bproj[t];
        for (int d = 0; d < Dn; d++) b += bemb[d] * Wproj[d * Fn + t];
        g_beff[t] = b;
    }
}

// ---------------- 1) fused front: enc(bf16) + P + mse; x shared via warp shuffle ----------------
__global__ void fused_front_kernel(const float* __restrict__ x,
                                   const float* __restrict__ Wemb,
                                   const float* __restrict__ bemb,
                                   float* __restrict__ P) {
    __shared__ float sW[Fn * Dn];
    __shared__ float sb[Dn];
    __shared__ float sWe[Fn * Fn];
    __shared__ float sbe[Fn];
    __shared__ float sred[256];
    int t = threadIdx.x;
    for (int i = t; i < Fn * Dn; i += 256) sW[i] = Wemb[i];
    if (t < Dn) sb[t] = bemb[t];
    if (t < Fn * Fn) sWe[t] = g_Weff[t];
    if (t < Fn) sbe[t] = g_beff[t];
    __syncthreads();

    const int lane = t & 31;
    int gt = blockIdx.x * 256 + t;
    int r  = gt >> 3;                 // row handled by this thread
    int dg = t & 7;

    // one coalesced load per thread; row's 8 floats live in 8 consecutive lanes
    float v = x[(size_t)blockIdx.x * 256 + t];
    float xv[Fn];
#pragma unroll
    for (int f = 0; f < Fn; f++)
        xv[f] = __shfl_sync(0xffffffffu, v, (lane & 24) + f);

    __nv_bfloat16 ev[8];
#pragma unroll
    for (int j = 0; j < 8; j++) {
        int d = dg * 8 + j;
        float acc = sb[d];
#pragma unroll
        for (int f = 0; f < Fn; f++) acc += xv[f] * sW[f * Dn + d];
        ev[j] = __float2bfloat16(acc);
    }
    *reinterpret_cast<uint4*>(&g_xenc_bf16[(size_t)r * Dn + dg * 8]) =
        *reinterpret_cast<uint4*>(ev);

    float p = sbe[dg];
#pragma unroll
    for (int g = 0; g < Fn; g++) p += xv[g] * sWe[g * Fn + dg];
    P[(size_t)r * Fn + dg] = p;
    float dv = p - xv[dg];
    float part = block_reduce_sum(dv * dv, sred);
    if (t == 0) g_part_mse[blockIdx.x] = part;
}

// ---------------- 2) per-sample diff2 contribution (R4 exact) ----------------
__global__ void c2_kernel(const float* __restrict__ P) {
    int wid  = threadIdx.x >> 5;
    int lane = threadIdx.x & 31;
    int j = blockIdx.x * 4 + wid;
    const float* p = P + (size_t)j * (Sn * Fn);
    float acc = 0.f;
    for (int i = lane; i < (Sn - 1) * Fn; i += 32) {
        float d = p[i + Fn] - p[i];
        acc += d * d;
    }
#pragma unroll
    for (int o = 16; o > 0; o >>= 1) acc += __shfl_down_sync(0xffffffffu, acc, o);
    if (lane == 0) g_c2[j] = acc;
}

// ---------------- 3) gram (R4 measured-best: 128x128 tiles, 2-stage, ldmatrix) ----------------
#define GK 64
#define ROWPAD 72
#define TILE_ELEMS (128 * ROWPAD)

__global__ __launch_bounds__(256, 2) void gram_kernel() {
    extern __shared__ __nv_bfloat16 sh[];
    const uint32_t shbase = (uint32_t)__cvta_generic_to_shared(sh);

    const int tid  = threadIdx.x;
    const int wid  = tid >> 5;
    const int lane = tid & 31;
    const int wm = wid >> 2;
    const int wn = wid & 3;

    int tl = blockIdx.x;                  // 0..527 upper-tri tiles
    int i = (int)((65.0f - sqrtf(65.0f * 65.0f - 8.0f * (float)tl)) * 0.5f);
    while (i * 32 - i * (i - 1) / 2 > tl) i--;
    while ((i + 1) * 32 - (i + 1) * i / 2 <= tl) i++;
    int j = i + (tl - (i * 32 - i * (i - 1) / 2));
    const int rowBase = i * 128;
    const int colBase = j * 128;
    const bool diag = (i == j);

    const __nv_bfloat16* Xe = g_xenc_bf16;

    float acc[4][4][4];
#pragma unroll
    for (int a = 0; a < 4; a++)
#pragma unroll
        for (int b = 0; b < 4; b++)
#pragma unroll
            for (int c = 0; c < 4; c++) acc[a][b][c] = 0.f;

    auto load_tile = [&](int buf, int kt) {
        int k0 = kt * GK;
        uint32_t sA = shbase + (uint32_t)(buf * 2 * TILE_ELEMS) * 2u;
        uint32_t sB = sA + TILE_ELEMS * 2u;
#pragma unroll
        for (int it = 0; it < 4; it++) {
            int c = tid + it * 256;
            int r = c >> 3, g = c & 7;
            cp_async16(sA + (uint32_t)(r * ROWPAD + g * 8) * 2u,
                       Xe + (size_t)(rowBase + r) * Ln + k0 + g * 8);
            cp_async16(sB + (uint32_t)(r * ROWPAD + g * 8) * 2u,
                       Xe + (size_t)(colBase + r) * Ln + k0 + g * 8);
        }
        asm volatile("cp.async.commit_group;\n" ::: "memory");
    };

    load_tile(0, 0);

    const int aRow = lane & 15;
    const int aCol = (lane >> 4) << 3;
    const int bRow = ((lane >> 4) << 3) + (lane & 7);
    const int bCol = ((lane >> 3) & 1) << 3;

    const int NT = Ln / GK;   // 64
    for (int kt = 0; kt < NT; kt++) {
        if (kt + 1 < NT) {
            load_tile((kt + 1) & 1, kt + 1);
            asm volatile("cp.async.wait_group 1;\n" ::: "memory");
        } else {
            asm volatile("cp.async.wait_group 0;\n" ::: "memory");
        }
        __syncthreads();

        uint32_t A  = shbase + (uint32_t)((kt & 1) * 2 * TILE_ELEMS) * 2u;
        uint32_t Bs = A + TILE_ELEMS * 2u;
#pragma unroll
        for (int ks = 0; ks < 4; ks++) {
            int e0 = ks * 16;
            uint32_t a[4][4];
#pragma unroll
            for (int mt = 0; mt < 4; mt++) {
                int r0 = wm * 64 + mt * 16;
                ldsm_x4(a[mt], A + (uint32_t)((r0 + aRow) * ROWPAD + e0 + aCol) * 2u);
            }
            uint32_t bb[4][2];
#pragma unroll
            for (int p = 0; p < 2; p++) {
                int n0 = wn * 32 + p * 16;
                uint32_t tmp[4];
                ldsm_x4(tmp, Bs + (uint32_t)((n0 + bRow) * ROWPAD + e0 + bCol) * 2u);
                bb[p * 2][0] = tmp[0];     bb[p * 2][1] = tmp[1];
                bb[p * 2 + 1][0] = tmp[2]; bb[p * 2 + 1][1] = tmp[3];
            }
#pragma unroll
            for (int mt = 0; mt < 4; mt++)
#pragma unroll
                for (int nt = 0; nt < 4; nt++)
                    mma16816(&acc[mt][nt][0], &a[mt][0], &bb[nt][0]);
        }
        __syncthreads();
    }

    const int rq = lane >> 2;
    const int kp = (lane & 3) << 1;
#pragma unroll
    for (int mt = 0; mt < 4; mt++) {
#pragma unroll
        for (int nt = 0; nt < 4; nt++) {
            int row = rowBase + wm * 64 + mt * 16 + rq;
            int col = colBase + wn * 32 + nt * 8 + kp;
            *reinterpret_cast<float2*>(&g_gram[(size_t)row * Bn + col]) =
                make_float2(acc[mt][nt][0], acc[mt][nt][1]);
            *reinterpret_cast<float2*>(&g_gram[(size_t)(row + 8) * Bn + col]) =
                make_float2(acc[mt][nt][2], acc[mt][nt][3]);
            if (!diag) {
                g_gram[(size_t)col * Bn + row]           = acc[mt][nt][0];
                g_gram[(size_t)(col + 1) * Bn + row]     = acc[mt][nt][1];
                g_gram[(size_t)col * Bn + row + 8]       = acc[mt][nt][2];
                g_gram[(size_t)(col + 1) * Bn + row + 8] = acc[mt][nt][3];
            }
        }
    }
}

// ---------------- 4) top-16 via radix/histogram select, 512 threads ----------------
// 8 keys/thread. 2048-bucket histogram of top-11 key bits. Suffix scan ->
// threshold bucket; candidates compacted; warp 0 extracts exact top-16.
__global__ __launch_bounds__(512, 3) void topk_kernel() {
    __shared__ uint32_t hist[2048];            // 8 KB
    __shared__ uint32_t partial[256];
    __shared__ int      s_bth;
    __shared__ int      s_cnt;
    __shared__ unsigned long long cand[TK_CAP];
    __shared__ unsigned long long wmax[16];
    const int b = blockIdx.x;
    const int t = threadIdx.x;
    const int lane = t & 31, wid = t >> 5;

    // load 8 row elements -> keys (registers: 8 x u32)
    uint32_t key[8];
    {
        const float* row = &g_gram[(size_t)b * Bn + t * 8];
#pragma unroll
        for (int q = 0; q < 2; q++) {
            float4 v = reinterpret_cast<const float4*>(row)[q];
            key[q * 4]     = fkey(v.x);
            key[q * 4 + 1] = fkey(v.y);
            key[q * 4 + 2] = fkey(v.z);
            key[q * 4 + 3] = fkey(v.w);
        }
        if ((b >> 3) == t) key[b & 7] = 0u;    // exclude diagonal
    }

    // zero histogram + counter
#pragma unroll
    for (int i = 0; i < 4; i++) hist[t + i * 512] = 0;
    if (t == 0) s_cnt = 0;
    __syncthreads();

    // build histogram (spread smem atomics)
#pragma unroll
    for (int q = 0; q < 8; q++) atomicAdd(&hist[key[q] >> 21], 1u);
    __syncthreads();

    // chunk partials from the top: chunk c covers buckets [2047-8c .. 2040-8c]
    if (t < 256) {
        uint32_t s = 0;
        int base = 2047 - 8 * t;
#pragma unroll
        for (int k = 0; k < 8; k++) s += hist[base - k];
        partial[t] = s;
    }
    __syncthreads();

    if (t == 0) {
        uint32_t cum = 0;
        int bth = 0;
        for (int c = 0; c < 256; c++) {
            uint32_t nc = cum + partial[c];
            if (nc >= (uint32_t)Kn) {
                int bb = 2047 - 8 * c;
                for (int k = 0; k < 8; k++) {
                    cum += hist[bb - k];
                    if (cum >= (uint32_t)Kn) { bth = bb - k; break; }
                }
                break;
            }
            cum = nc;
        }
        s_bth = bth;
    }
    __syncthreads();

    // compact candidates
    const uint32_t thrsh = (uint32_t)s_bth << 21;
#pragma unroll
    for (int q = 0; q < 8; q++) {
        if (key[q] >= thrsh) {
            int pos = atomicAdd(&s_cnt, 1);
            if (pos < TK_CAP)
                cand[pos] = ((unsigned long long)key[q] << 32) |
                            (unsigned long long)(0xFFFFFFFFu - (uint32_t)(t * 8 + q));
        }
    }
    __syncthreads();
    const int ncand = s_cnt;

    if (ncand <= TK_CAP) {
        if (wid == 0) {
            unsigned long long c6[6];
#pragma unroll
            for (int q = 0; q < 6; q++) {
                int p = lane + q * 32;
                c6[q] = (p < ncand) ? cand[p] : 0ull;
            }
            unsigned long long lmax = c6[0];
#pragma unroll
            for (int q = 1; q < 6; q++) if (c6[q] > lmax) lmax = c6[q];

            for (int it = 0; it < Kn; it++) {
                unsigned long long best = lmax;
#pragma unroll
                for (int o = 16; o > 0; o >>= 1) {
                    unsigned long long v = __shfl_xor_sync(0xffffffffu, best, o);
                    if (v > best) best = v;
                }
                if (lane == 0)
                    g_topidx[b * Kn + it] =
                        (int)(0xFFFFFFFFu - (uint32_t)(best & 0xFFFFFFFFull));
                if (lmax == best) {
#pragma unroll
                    for (int q = 0; q < 6; q++) if (c6[q] == best) c6[q] = 0ull;
                    lmax = c6[0];
#pragma unroll
                    for (int q = 1; q < 6; q++) if (c6[q] > lmax) lmax = c6[q];
                }
            }
        }
    } else {
        // fallback: block-wide extraction using keys (uniform branch, 512 thr)
        unsigned long long loc =
            ((unsigned long long)key[0] << 32) |
            (unsigned long long)(0xFFFFFFFFu - (uint32_t)(t * 8));
#pragma unroll
        for (int q = 1; q < 8; q++) {
            unsigned long long p = ((unsigned long long)key[q] << 32) |
                (unsigned long long)(0xFFFFFFFFu - (uint32_t)(t * 8 + q));
            if (p > loc) loc = p;
        }
        for (int it = 0; it < Kn; it++) {
            unsigned long long best = loc;
#pragma unroll
            for (int o = 16; o > 0; o >>= 1) {
                unsigned long long v = __shfl_down_sync(0xffffffffu, best, o);
                if (v > best) best = v;
            }
            if (lane == 0) wmax[wid] = best;
            __syncthreads();
            best = wmax[0];
#pragma unroll
            for (int w = 1; w < 16; w++) if (wmax[w] > best) best = wmax[w];
            const int idx = (int)(0xFFFFFFFFu - (uint32_t)(best & 0xFFFFFFFFull));
            if (t == 0) g_topidx[b * Kn + it] = idx;
            if ((idx >> 3) == t) {
#pragma unroll
                for (int q = 0; q < 8; q++) if ((idx & 7) == q) key[q] = 0u;
                loc = ((unsigned long long)key[0] << 32) |
                      (unsigned long long)(0xFFFFFFFFu - (uint32_t)(t * 8));
#pragma unroll
                for (int q = 1; q < 8; q++) {
                    unsigned long long p = ((unsigned long long)key[q] << 32) |
                        (unsigned long long)(0xFFFFFFFFu - (uint32_t)(t * 8 + q));
                    if (p > loc) loc = p;
                }
            }
            __syncthreads();
        }
    }
}

// ---------------- 5) diff1/diff2 partials (R4 exact) ----------------
__global__ void diff_kernel(const float* __restrict__ P) {
    __shared__ int   idx[Kn];
    __shared__ float sred[128];
    int b = blockIdx.x;
    int t = threadIdx.x;
    if (t < Kn) idx[t] = g_topidx[b * Kn + t];
    __syncthreads();

    float a1 = 0.f;
    for (int k = 0; k < Kn - 1; k++) {
        const float* u = P + (size_t)idx[k] * (Sn * Fn);
        const float* v = P + (size_t)idx[k + 1] * (Sn * Fn);
        for (int i = t; i < Sn * Fn; i += 128) {
            float d = v[i] - u[i];
            a1 += d * d;
        }
    }
    float s1 = block_reduce_sum(a1, sred);
    if (t == 0) g_part_d1[b] = s1;
    __syncthreads();

    float a2 = (t < Kn) ? g_c2[idx[t]] : 0.f;
    float s2 = block_reduce_sum(a2, sred);
    if (t == 0) g_part_d2[b] = s2;
}

// ---------------- 6) deterministic final reduce ----------------
__global__ void final_kernel(float* __restrict__ out, int write_loss) {
    __shared__ float s[256];
    int t = threadIdx.x;
    float m = 0.f, d1 = 0.f, d2 = 0.f;
    for (int i = t; i < 8192; i += 256) m  += g_part_mse[i];
    for (int i = t; i < Bn;   i += 256) d1 += g_part_d1[i];
    for (int i = t; i < Bn;   i += 256) d2 += g_part_d2[i];

    float ms = block_reduce_sum(m, s);  __syncthreads();
    float s1 = block_reduce_sum(d1, s); __syncthreads();
    float s2 = block_reduce_sum(d2, s);
    if (t == 0 && write_loss) {
        float loss = ms / 2097152.0f
                   + s1 / 31457280.0f
                   + s2 / 33030144.0f;
        out[0] = loss;
    }
}

// ---------------- launch (topk at #4 so ncu measures it) ----------------
extern "C" void kernel_launch(void* const* d_in, const int* in_sizes, int n_in,
                              void* d_out, int out_size) {
    (void)in_sizes; (void)n_in;
    const float* x     = (const float*)d_in[0];
    const float* Wemb  = (const float*)d_in[1];
    const float* bemb  = (const float*)d_in[2];
    const float* Wproj = (const float*)d_in[3];
    const float* bproj = (const float*)d_in[4];
    float* out = (float*)d_out;

    float* P;
    int write_loss;
    float* Pfallback;
    cudaGetSymbolAddress((void**)&Pfallback, g_P);
    if (out_size >= PN + 1)      { P = out + 1;  write_loss = 1; }
    else if (out_size == PN)     { P = out;      write_loss = 0; }
    else                         { P = Pfallback; write_loss = 1; }

    static int smem_set = 0;
    if (!smem_set) {
        cudaFuncSetAttribute(gram_kernel,
                             cudaFuncAttributeMaxDynamicSharedMemorySize, 73728);
        smem_set = 1;
    }

    weff_kernel<<<1, 64>>>(Wemb, bemb, Wproj, bproj);          // 1
    fused_front_kernel<<<8192, 256>>>(x, Wemb, bemb, P);       // 2
    gram_kernel<<<528, 256, 73728>>>();                        // 3
    topk_kernel<<<Bn, 512>>>();                                // 4  <- profiled
    c2_kernel<<<1024, 128>>>(P);                               // 5
    diff_kernel<<<Bn, 128>>>(P);                               // 6
    final_kernel<<<1, 256>>>(out, write_loss);                 // 7
}

// round 17
// speedup vs baseline: 1.0595x; 1.0595x over previous
#include <cuda_runtime.h>
#include <cuda_bf16.h>
#include <cstdint>

#define Bn 4096
#define Sn 64
#define Fn 8
#define Dn 64
#define Kn 16
#define Ln 4096
#define PN (Bn*Sn*Fn)
#define TK_CAP 192

// ---------------- device scratch ----------------
__device__ __nv_bfloat16   g_xenc_bf16[Bn * Ln];         // 32 MB
__device__ float           g_gram[Bn * Bn];              // 64 MB
__device__ int             g_topidx[Bn * Kn];
__device__ float           g_c2[Bn];
__device__ float           g_part_mse[8192];
__device__ float           g_part_d1[Bn];
__device__ float           g_part_d2[Bn];
__device__ float           g_Weff[Fn * Fn];
__device__ float           g_beff[Fn];
__device__ float           g_P[PN];                      // fallback

// ---------------- helpers ----------------
__device__ __forceinline__ float block_reduce_sum(float v, float* s) {
    int t = threadIdx.x;
    s[t] = v;
    __syncthreads();
    for (int k = blockDim.x >> 1; k > 0; k >>= 1) {
        if (t < k) s[t] += s[t + k];
        __syncthreads();
    }
    return s[0];
}

__device__ __forceinline__ void cp_async16(uint32_t dst, const void* src) {
    asm volatile("cp.async.cg.shared.global [%0], [%1], 16;\n" :: "r"(dst), "l"(src) : "memory");
}

__device__ __forceinline__ void mma16816(float* c, const uint32_t* a, const uint32_t* b) {
    asm volatile(
        "mma.sync.aligned.m16n8k16.row.col.f32.bf16.bf16.f32 "
        "{%0,%1,%2,%3}, {%4,%5,%6,%7}, {%8,%9}, {%0,%1,%2,%3};"
        : "+f"(c[0]), "+f"(c[1]), "+f"(c[2]), "+f"(c[3])
        : "r"(a[0]), "r"(a[1]), "r"(a[2]), "r"(a[3]), "r"(b[0]), "r"(b[1]));
}

__device__ __forceinline__ void ldsm_x4(uint32_t* r, uint32_t addr) {
    asm volatile("ldmatrix.sync.aligned.m8n8.x4.shared.b16 {%0,%1,%2,%3}, [%4];"
                 : "=r"(r[0]), "=r"(r[1]), "=r"(r[2]), "=r"(r[3]) : "r"(addr));
}

// monotone float->u32 transform: larger float -> larger uint
__device__ __forceinline__ uint32_t fkey(float v) {
    uint32_t b = __float_as_uint(v);
    return b ^ ((b >> 31) ? 0xFFFFFFFFu : 0x80000000u);
}

// ---------------- 0) W_eff = W_emb @ W_proj ; b_eff ----------------
__global__ void weff_kernel(const float* __restrict__ Wemb,
                            const float* __restrict__ bemb,
                            const float* __restrict__ Wproj,
                            const float* __restrict__ bproj) {
    int t = threadIdx.x;
    int g = t >> 3, f = t & 7;
    float acc = 0.f;
#pragma unroll
    for (int d = 0; d < Dn; d++) acc += Wemb[g * Dn + d] * Wproj[d * Fn + f];
    g_Weff[g * Fn + f] = acc;
    if (t < Fn) {
        float b = bproj[t];
        for (int d = 0; d < Dn; d++) b += bemb[d] * Wproj[d * Fn + t];
        g_beff[t] = b;
    }
}

// ---------------- 1) fused front: enc(bf16) + P + mse; x shared via warp shuffle ----------------
__global__ void fused_front_kernel(const float* __restrict__ x,
                                   const float* __restrict__ Wemb,
                                   const float* __restrict__ bemb,
                                   float* __restrict__ P) {
    __shared__ float sW[Fn * Dn];
    __shared__ float sb[Dn];
    __shared__ float sWe[Fn * Fn];
    __shared__ float sbe[Fn];
    __shared__ float sred[256];
    int t = threadIdx.x;
    for (int i = t; i < Fn * Dn; i += 256) sW[i] = Wemb[i];
    if (t < Dn) sb[t] = bemb[t];
    if (t < Fn * Fn) sWe[t] = g_Weff[t];
    if (t < Fn) sbe[t] = g_beff[t];
    __syncthreads();

    const int lane = t & 31;
    int gt = blockIdx.x * 256 + t;
    int r  = gt >> 3;
    int dg = t & 7;

    float v = x[(size_t)blockIdx.x * 256 + t];
    float xv[Fn];
#pragma unroll
    for (int f = 0; f < Fn; f++)
        xv[f] = __shfl_sync(0xffffffffu, v, (lane & 24) + f);

    __nv_bfloat16 ev[8];
#pragma unroll
    for (int j = 0; j < 8; j++) {
        int d = dg * 8 + j;
        float acc = sb[d];
#pragma unroll
        for (int f = 0; f < Fn; f++) acc += xv[f] * sW[f * Dn + d];
        ev[j] = __float2bfloat16(acc);
    }
    *reinterpret_cast<uint4*>(&g_xenc_bf16[(size_t)r * Dn + dg * 8]) =
        *reinterpret_cast<uint4*>(ev);

    float p = sbe[dg];
#pragma unroll
    for (int g = 0; g < Fn; g++) p += xv[g] * sWe[g * Fn + dg];
    P[(size_t)r * Fn + dg] = p;
    float dv = p - xv[dg];
    float part = block_reduce_sum(dv * dv, sred);
    if (t == 0) g_part_mse[blockIdx.x] = part;
}

// ---------------- 2) per-sample diff2 contribution (R4 exact) ----------------
__global__ void c2_kernel(const float* __restrict__ P) {
    int wid  = threadIdx.x >> 5;
    int lane = threadIdx.x & 31;
    int j = blockIdx.x * 4 + wid;
    const float* p = P + (size_t)j * (Sn * Fn);
    float acc = 0.f;
    for (int i = lane; i < (Sn - 1) * Fn; i += 32) {
        float d = p[i + Fn] - p[i];
        acc += d * d;
    }
#pragma unroll
    for (int o = 16; o > 0; o >>= 1) acc += __shfl_down_sync(0xffffffffu, acc, o);
    if (lane == 0) g_c2[j] = acc;
}

// ---------------- 3) gram (R4 measured-best: 128x128 tiles, 2-stage, ldmatrix) ----------------
#define GK 64
#define ROWPAD 72
#define TILE_ELEMS (128 * ROWPAD)

__global__ __launch_bounds__(256, 2) void gram_kernel() {
    extern __shared__ __nv_bfloat16 sh[];
    const uint32_t shbase = (uint32_t)__cvta_generic_to_shared(sh);

    const int tid  = threadIdx.x;
    const int wid  = tid >> 5;
    const int lane = tid & 31;
    const int wm = wid >> 2;
    const int wn = wid & 3;

    int tl = blockIdx.x;                  // 0..527 upper-tri tiles
    int i = (int)((65.0f - sqrtf(65.0f * 65.0f - 8.0f * (float)tl)) * 0.5f);
    while (i * 32 - i * (i - 1) / 2 > tl) i--;
    while ((i + 1) * 32 - (i + 1) * i / 2 <= tl) i++;
    int j = i + (tl - (i * 32 - i * (i - 1) / 2));
    const int rowBase = i * 128;
    const int colBase = j * 128;
    const bool diag = (i == j);

    const __nv_bfloat16* Xe = g_xenc_bf16;

    float acc[4][4][4];
#pragma unroll
    for (int a = 0; a < 4; a++)
#pragma unroll
        for (int b = 0; b < 4; b++)
#pragma unroll
            for (int c = 0; c < 4; c++) acc[a][b][c] = 0.f;

    auto load_tile = [&](int buf, int kt) {
        int k0 = kt * GK;
        uint32_t sA = shbase + (uint32_t)(buf * 2 * TILE_ELEMS) * 2u;
        uint32_t sB = sA + TILE_ELEMS * 2u;
#pragma unroll
        for (int it = 0; it < 4; it++) {
            int c = tid + it * 256;
            int r = c >> 3, g = c & 7;
            cp_async16(sA + (uint32_t)(r * ROWPAD + g * 8) * 2u,
                       Xe + (size_t)(rowBase + r) * Ln + k0 + g * 8);
            cp_async16(sB + (uint32_t)(r * ROWPAD + g * 8) * 2u,
                       Xe + (size_t)(colBase + r) * Ln + k0 + g * 8);
        }
        asm volatile("cp.async.commit_group;\n" ::: "memory");
    };

    load_tile(0, 0);

    const int aRow = lane & 15;
    const int aCol = (lane >> 4) << 3;
    const int bRow = ((lane >> 4) << 3) + (lane & 7);
    const int bCol = ((lane >> 3) & 1) << 3;

    const int NT = Ln / GK;   // 64
    for (int kt = 0; kt < NT; kt++) {
        if (kt + 1 < NT) {
            load_tile((kt + 1) & 1, kt + 1);
            asm volatile("cp.async.wait_group 1;\n" ::: "memory");
        } else {
            asm volatile("cp.async.wait_group 0;\n" ::: "memory");
        }
        __syncthreads();

        uint32_t A  = shbase + (uint32_t)((kt & 1) * 2 * TILE_ELEMS) * 2u;
        uint32_t Bs = A + TILE_ELEMS * 2u;
#pragma unroll
        for (int ks = 0; ks < 4; ks++) {
            int e0 = ks * 16;
            uint32_t a[4][4];
#pragma unroll
            for (int mt = 0; mt < 4; mt++) {
                int r0 = wm * 64 + mt * 16;
                ldsm_x4(a[mt], A + (uint32_t)((r0 + aRow) * ROWPAD + e0 + aCol) * 2u);
            }
            uint32_t bb[4][2];
#pragma unroll
            for (int p = 0; p < 2; p++) {
                int n0 = wn * 32 + p * 16;
                uint32_t tmp[4];
                ldsm_x4(tmp, Bs + (uint32_t)((n0 + bRow) * ROWPAD + e0 + bCol) * 2u);
                bb[p * 2][0] = tmp[0];     bb[p * 2][1] = tmp[1];
                bb[p * 2 + 1][0] = tmp[2]; bb[p * 2 + 1][1] = tmp[3];
            }
#pragma unroll
            for (int mt = 0; mt < 4; mt++)
#pragma unroll
                for (int nt = 0; nt < 4; nt++)
                    mma16816(&acc[mt][nt][0], &a[mt][0], &bb[nt][0]);
        }
        __syncthreads();
    }

    const int rq = lane >> 2;
    const int kp = (lane & 3) << 1;
#pragma unroll
    for (int mt = 0; mt < 4; mt++) {
#pragma unroll
        for (int nt = 0; nt < 4; nt++) {
            int row = rowBase + wm * 64 + mt * 16 + rq;
            int col = colBase + wn * 32 + nt * 8 + kp;
            *reinterpret_cast<float2*>(&g_gram[(size_t)row * Bn + col]) =
                make_float2(acc[mt][nt][0], acc[mt][nt][1]);
            *reinterpret_cast<float2*>(&g_gram[(size_t)(row + 8) * Bn + col]) =
                make_float2(acc[mt][nt][2], acc[mt][nt][3]);
            if (!diag) {
                g_gram[(size_t)col * Bn + row]           = acc[mt][nt][0];
                g_gram[(size_t)(col + 1) * Bn + row]     = acc[mt][nt][1];
                g_gram[(size_t)col * Bn + row + 8]       = acc[mt][nt][2];
                g_gram[(size_t)(col + 1) * Bn + row + 8] = acc[mt][nt][3];
            }
        }
    }
}

// ---------------- 4) top-16 via radix/histogram select (R15 exact) ----------------
__global__ __launch_bounds__(256, 5) void topk_kernel() {
    __shared__ uint32_t hist[2048];            // 8 KB
    __shared__ uint32_t partial[256];
    __shared__ int      s_bth;
    __shared__ int      s_cnt;
    __shared__ unsigned long long cand[TK_CAP];
    __shared__ unsigned long long wmax[8];
    const int b = blockIdx.x;
    const int t = threadIdx.x;
    const int lane = t & 31, wid = t >> 5;

    uint32_t key[16];
    {
        const float* row = &g_gram[(size_t)b * Bn + t * 16];
#pragma unroll
        for (int q = 0; q < 4; q++) {
            float4 v = reinterpret_cast<const float4*>(row)[q];
            key[q * 4]     = fkey(v.x);
            key[q * 4 + 1] = fkey(v.y);
            key[q * 4 + 2] = fkey(v.z);
            key[q * 4 + 3] = fkey(v.w);
        }
        if ((b >> 4) == t) key[b & 15] = 0u;   // exclude diagonal
    }

#pragma unroll
    for (int i = 0; i < 8; i++) hist[t + i * 256] = 0;
    if (t == 0) s_cnt = 0;
    __syncthreads();

#pragma unroll
    for (int q = 0; q < 16; q++) atomicAdd(&hist[key[q] >> 21], 1u);
    __syncthreads();

    {
        uint32_t s = 0;
        int base = 2047 - 8 * t;
#pragma unroll
        for (int k = 0; k < 8; k++) s += hist[base - k];
        partial[t] = s;
    }
    __syncthreads();

    if (t == 0) {
        uint32_t cum = 0;
        int bth = 0;
        for (int c = 0; c < 256; c++) {
            uint32_t nc = cum + partial[c];
            if (nc >= (uint32_t)Kn) {
                int bb = 2047 - 8 * c;
                for (int k = 0; k < 8; k++) {
                    cum += hist[bb - k];
                    if (cum >= (uint32_t)Kn) { bth = bb - k; break; }
                }
                break;
            }
            cum = nc;
        }
        s_bth = bth;
    }
    __syncthreads();

    const uint32_t thrsh = (uint32_t)s_bth << 21;
#pragma unroll
    for (int q = 0; q < 16; q++) {
        if (key[q] >= thrsh) {
            int pos = atomicAdd(&s_cnt, 1);
            if (pos < TK_CAP)
                cand[pos] = ((unsigned long long)key[q] << 32) |
                            (unsigned long long)(0xFFFFFFFFu - (uint32_t)(t * 16 + q));
        }
    }
    __syncthreads();
    const int ncand = s_cnt;

    if (ncand <= TK_CAP) {
        if (wid == 0) {
            unsigned long long c6[6];
#pragma unroll
            for (int q = 0; q < 6; q++) {
                int p = lane + q * 32;
                c6[q] = (p < ncand) ? cand[p] : 0ull;
            }
            unsigned long long lmax = c6[0];
#pragma unroll
            for (int q = 1; q < 6; q++) if (c6[q] > lmax) lmax = c6[q];

            for (int it = 0; it < Kn; it++) {
                unsigned long long best = lmax;
#pragma unroll
                for (int o = 16; o > 0; o >>= 1) {
                    unsigned long long v = __shfl_xor_sync(0xffffffffu, best, o);
                    if (v > best) best = v;
                }
                if (lane == 0)
                    g_topidx[b * Kn + it] =
                        (int)(0xFFFFFFFFu - (uint32_t)(best & 0xFFFFFFFFull));
                if (lmax == best) {
#pragma unroll
                    for (int q = 0; q < 6; q++) if (c6[q] == best) c6[q] = 0ull;
                    lmax = c6[0];
#pragma unroll
                    for (int q = 1; q < 6; q++) if (c6[q] > lmax) lmax = c6[q];
                }
            }
        }
    } else {
        unsigned long long loc =
            ((unsigned long long)key[0] << 32) |
            (unsigned long long)(0xFFFFFFFFu - (uint32_t)(t * 16));
#pragma unroll
        for (int q = 1; q < 16; q++) {
            unsigned long long p = ((unsigned long long)key[q] << 32) |
                (unsigned long long)(0xFFFFFFFFu - (uint32_t)(t * 16 + q));
            if (p > loc) loc = p;
        }
        for (int it = 0; it < Kn; it++) {
            unsigned long long best = loc;
#pragma unroll
            for (int o = 16; o > 0; o >>= 1) {
                unsigned long long v = __shfl_down_sync(0xffffffffu, best, o);
                if (v > best) best = v;
            }
            if (lane == 0) wmax[wid] = best;
            __syncthreads();
            best = wmax[0];
#pragma unroll
            for (int w = 1; w < 8; w++) if (wmax[w] > best) best = wmax[w];
            const int idx = (int)(0xFFFFFFFFu - (uint32_t)(best & 0xFFFFFFFFull));
            if (t == 0) g_topidx[b * Kn + it] = idx;
            if ((idx >> 4) == t) {
#pragma unroll
                for (int q = 0; q < 16; q++) if ((idx & 15) == q) key[q] = 0u;
                loc = ((unsigned long long)key[0] << 32) |
                      (unsigned long long)(0xFFFFFFFFu - (uint32_t)(t * 16));
#pragma unroll
                for (int q = 1; q < 16; q++) {
                    unsigned long long p = ((unsigned long long)key[q] << 32) |
                        (unsigned long long)(0xFFFFFFFFu - (uint32_t)(t * 16 + q));
                    if (p > loc) loc = p;
                }
            }
            __syncthreads();
        }
    }
}

// ---------------- 5) diff1/diff2: barrier-free register chain (each row read once) ----------------
__global__ void diff_kernel(const float* __restrict__ P) {
    __shared__ int   idx[Kn];
    __shared__ float sred[128];
    const int b = blockIdx.x;
    const int t = threadIdx.x;
    if (t < Kn) idx[t] = g_topidx[b * Kn + t];
    __syncthreads();

    float prev[4];
    {
        const float* p0 = P + (size_t)idx[0] * (Sn * Fn);
#pragma unroll
        for (int jq = 0; jq < 4; jq++) prev[jq] = p0[t + 128 * jq];
    }

    float a1 = 0.f;
#pragma unroll 1
    for (int k = 1; k < Kn; k++) {
        const float* pk = P + (size_t)idx[k] * (Sn * Fn);
#pragma unroll
        for (int jq = 0; jq < 4; jq++) {
            float c = pk[t + 128 * jq];
            float d = c - prev[jq];
            a1 += d * d;
            prev[jq] = c;
        }
    }
    float s1 = block_reduce_sum(a1, sred);
    if (t == 0) g_part_d1[b] = s1;
    __syncthreads();

    float a2 = (t < Kn) ? g_c2[idx[t]] : 0.f;
    float s2 = block_reduce_sum(a2, sred);
    if (t == 0) g_part_d2[b] = s2;
}

// ---------------- 6) deterministic final reduce ----------------
__global__ void final_kernel(float* __restrict__ out, int write_loss) {
    __shared__ float s[256];
    int t = threadIdx.x;
    float m = 0.f, d1 = 0.f, d2 = 0.f;
    for (int i = t; i < 8192; i += 256) m  += g_part_mse[i];
    for (int i = t; i < Bn;   i += 256) d1 += g_part_d1[i];
    for (int i = t; i < Bn;   i += 256) d2 += g_part_d2[i];

    float ms = block_reduce_sum(m, s);  __syncthreads();
    float s1 = block_reduce_sum(d1, s); __syncthreads();
    float s2 = block_reduce_sum(d2, s);
    if (t == 0 && write_loss) {
        float loss = ms / 2097152.0f
                   + s1 / 31457280.0f
                   + s2 / 33030144.0f;
        out[0] = loss;
    }
}

// ---------------- launch (topk at #4 so ncu measures it) ----------------
extern "C" void kernel_launch(void* const* d_in, const int* in_sizes, int n_in,
                              void* d_out, int out_size) {
    (void)in_sizes; (void)n_in;
    const float* x     = (const float*)d_in[0];
    const float* Wemb  = (const float*)d_in[1];
    const float* bemb  = (const float*)d_in[2];
    const float* Wproj = (const float*)d_in[3];
    const float* bproj = (const float*)d_in[4];
    float* out = (float*)d_out;

    float* P;
    int write_loss;
    float* Pfallback;
    cudaGetSymbolAddress((void**)&Pfallback, g_P);
    if (out_size >= PN + 1)      { P = out + 1;  write_loss = 1; }
    else if (out_size == PN)     { P = out;      write_loss = 0; }
    else                         { P = Pfallback; write_loss = 1; }

    static int smem_set = 0;
    if (!smem_set) {
        cudaFuncSetAttribute(gram_kernel,
                             cudaFuncAttributeMaxDynamicSharedMemorySize, 73728);
        smem_set = 1;
    }

    weff_kernel<<<1, 64>>>(Wemb, bemb, Wproj, bproj);          // 1
    fused_front_kernel<<<8192, 256>>>(x, Wemb, bemb, P);       // 2
    gram_kernel<<<528, 256, 73728>>>();                        // 3
    topk_kernel<<<Bn, 256>>>();                                // 4  <- profiled
    c2_kernel<<<1024, 128>>>(P);                               // 5
    diff_kernel<<<Bn, 128>>>(P);                               // 6
    final_kernel<<<1, 256>>>(out, write_loss);                 // 7
}